// round 13
// baseline (speedup 1.0000x reference)
#include <cuda_runtime.h>
#include <cstdint>
#include <math.h>

// Shapes
#define BATCH 64
#define FEAT  2048
#define EDIM  64

// 16 batch groups x 8 feature chunks = 128 CTAs (classic launch, NO cluster).
// The 8 CTAs of a group combine via L2-resident global scratch + per-group
// atomic ticket; the last-arriving CTA of each group does the epilogue.
#define NB_ROWS 4
#define NFC     8
#define FCHUNK  (FEAT / NFC)                 // 256
#define NGRP    (BATCH / NB_ROWS)            // 16
#define GRID    (NGRP * NFC)                 // 128
#define NTHREADS 256                         // 16 fg x 16 dq

// Scratch: partials laid out so the reducer reads the 8 fc-partials of one
// (b,d) as two contiguous float4s. Fully overwritten every launch.
__device__ float g_S[NGRP][NB_ROWS][EDIM][NFC];   // 128 KB
__device__ float g_L[NGRP][NFC][NB_ROWS];         //   2 KB
__device__ unsigned int g_tick[NGRP][32];         // one counter per 128B line

__global__ void __launch_bounds__(NTHREADS, 1)
fm_ticket(const float* __restrict__ data,    // (BATCH, FEAT)
          const float* __restrict__ embed,   // (FEAT, EDIM)
          const float* __restrict__ bias,    // (FEAT,)
          const float* __restrict__ gbias,   // (1,)
          float* __restrict__ out)           // (BATCH,)
{
    __shared__ float sh_x[NB_ROWS][FCHUNK];          //  4 KB
    __shared__ float shp[16][NB_ROWS][EDIM + 4];     // ~17 KB
    __shared__ float linT[NB_ROWS][2];
    __shared__ float fin[NB_ROWS][2];
    __shared__ unsigned int sh_last;

    const int tid = threadIdx.x;
    const int bg  = blockIdx.x >> 3;   // batch group 0..15
    const int fc  = blockIdx.x & 7;    // feature chunk 0..7
    const int b0  = bg * NB_ROWS;
    const int f0  = fc * FCHUNK;

    // --- Prefetch embed into registers FIRST (identical to R12). ---
    const int fg = tid >> 4;       // 0..15, 16 features each
    const int dq = tid & 15;       // 0..15
    const int d0 = dq * 4;

    float4 v[16];
#pragma unroll
    for (int j = 0; j < 16; j++) {
        const int fl = fg * 16 + j;
        v[j] = *reinterpret_cast<const float4*>(&embed[(f0 + fl) * EDIM + d0]);
    }

    // --- Concurrently: stage x into shared + fold the bias dot-product. ---
    {
        const int r = tid >> 6, c = tid & 63;
        const float4 x4 = *reinterpret_cast<const float4*>(&data[(b0 + r) * FEAT + f0 + c * 4]);
        *reinterpret_cast<float4*>(&sh_x[r][c * 4]) = x4;
        const float4 bb = *reinterpret_cast<const float4*>(&bias[f0 + c * 4]);
        float p = x4.x * bb.x + x4.y * bb.y + x4.z * bb.z + x4.w * bb.w;
#pragma unroll
        for (int o = 16; o; o >>= 1) p += __shfl_xor_sync(0xffffffffu, p, o);
        if ((tid & 31) == 0) linT[r][(tid >> 5) & 1] = p;
    }
    __syncthreads();

    // --- Partial GEMM from registers: each prefetched float4 feeds 16 FFMA. ---
    float acc[NB_ROWS][4];
#pragma unroll
    for (int r = 0; r < NB_ROWS; r++)
#pragma unroll
        for (int i = 0; i < 4; i++) acc[r][i] = 0.0f;

#pragma unroll
    for (int j = 0; j < 16; j++) {
        const int fl = fg * 16 + j;
#pragma unroll
        for (int r = 0; r < NB_ROWS; r++) {
            const float xf = sh_x[r][fl];
            acc[r][0] = fmaf(xf, v[j].x, acc[r][0]);
            acc[r][1] = fmaf(xf, v[j].y, acc[r][1]);
            acc[r][2] = fmaf(xf, v[j].z, acc[r][2]);
            acc[r][3] = fmaf(xf, v[j].w, acc[r][3]);
        }
    }

#pragma unroll
    for (int r = 0; r < NB_ROWS; r++) {
        float4 w;
        w.x = acc[r][0]; w.y = acc[r][1]; w.z = acc[r][2]; w.w = acc[r][3];
        *reinterpret_cast<float4*>(&shp[fg][r][d0]) = w;
    }
    __syncthreads();

    // --- Cross-fg reduce -> this CTA's partial S; publish to global scratch. ---
    {
        const int r = tid >> 6, d = tid & 63;
        float s = 0.0f;
#pragma unroll
        for (int g = 0; g < 16; g++) s += shp[g][r][d];
        g_S[bg][r][d][fc] = s;
    }
    if (tid < NB_ROWS) {
        g_L[bg][fc][tid] = linT[tid][0] + linT[tid][1];
    }

    // --- Per-group ticket: release our stores, take a ticket; only the
    // group's LAST arrival continues (the other 7 CTAs exit immediately). ---
    __threadfence();
    __syncthreads();
    if (tid == 0) {
        const unsigned int t = atomicAdd(&g_tick[bg][0], 1);
        sh_last = (t == NFC - 1) ? 1u : 0u;
    }
    __syncthreads();
    if (!sh_last) return;
    if (tid == 0) g_tick[bg][0] = 0;   // reset for next graph replay (sole reader)
    __threadfence();                   // order ticket observation before data reads

    // --- Group epilogue: combine 8 chunk-partials (2x LDG.128 per (b,d)),
    // square-sum over d, add linear + global bias, sigmoid. ---
    {
        const int r = tid >> 6, d = tid & 63;
        const float4 s0 = __ldcg(reinterpret_cast<const float4*>(&g_S[bg][r][d][0]));
        const float4 s1 = __ldcg(reinterpret_cast<const float4*>(&g_S[bg][r][d][4]));
        const float s = ((s0.x + s0.y) + (s0.z + s0.w)) + ((s1.x + s1.y) + (s1.z + s1.w));
        float sq = s * s;
#pragma unroll
        for (int o = 16; o; o >>= 1) sq += __shfl_xor_sync(0xffffffffu, sq, o);
        if ((tid & 31) == 0) fin[r][(tid >> 5) & 1] = sq;
    }
    __syncthreads();

    if (tid < NB_ROWS) {
        float lin = 0.0f;
#pragma unroll
        for (int k = 0; k < NFC; k++) lin += __ldcg(&g_L[bg][k][tid]);
        const float z = gbias[0] + lin + fin[tid][0] + fin[tid][1];
        out[b0 + tid] = 1.0f / (1.0f + __expf(-z));
    }
}

extern "C" void kernel_launch(void* const* d_in, const int* in_sizes, int n_in,
                              void* d_out, int out_size) {
    const float* data  = (const float*)d_in[0];
    const float* embed = (const float*)d_in[1];
    const float* bias  = (const float*)d_in[2];
    const float* gbias = (const float*)d_in[3];
    float* out = (float*)d_out;

    fm_ticket<<<GRID, NTHREADS>>>(data, embed, bias, gbias, out);
}